// round 14
// baseline (speedup 1.0000x reference)
#include <cuda_runtime.h>
#include <cuda_bf16.h>
#include <cstdint>
#include <cstddef>

#define NN     50000
#define NE     800000
#define INC    128
#define HID    64
#define HEADS  4
#define D1     256          // HEADS*HID
#define OUTC   10
#define NG     500
#define NEG    0.2f

// ---------------- scratch (device globals; allocation-free) ----------------
__device__ __align__(16) __nv_bfloat16 g_h1b  [NN * D1];   // x @ W1  (bf16)
__device__ __align__(16) __nv_bfloat16 g_out1b[NN * D1];   // relu(GAT1+b1) bf16
__device__ __align__(16) __nv_bfloat16 g_h2b  [NN * HID];  // out1 @ W2 (bf16)
__device__ __align__(16) float g_als1[NN * HEADS];
__device__ __align__(16) float g_ald1[NN * HEADS];
__device__ float g_als2[NN], g_ald2[NN];
__device__ __align__(16) float g_pool[NG * HID];

// index handling + CSR (dst-sorted)
__device__ int g_is64;
__device__ int g_src[NE];
__device__ int g_dst[NE];
__device__ int g_bat[NN];
__device__ int g_deg[NN];
__device__ int g_row[NN + 1];
__device__ int g_cur[NN];
__device__ int g_csr_src[NE];

// ---------------- helpers ----------------
__device__ __forceinline__ float leaky(float v) { return v > 0.f ? v : NEG * v; }

__device__ __forceinline__ void red4(float* p, float4 v) {
    asm volatile("red.global.add.v4.f32 [%0], {%1,%2,%3,%4};"
                 :: "l"(p), "f"(v.x), "f"(v.y), "f"(v.z), "f"(v.w) : "memory");
}

__device__ __forceinline__ void unp8(uint4 u, float* f) {
    float2 p;
    p = __bfloat1622float2(*(const __nv_bfloat162*)&u.x); f[0] = p.x; f[1] = p.y;
    p = __bfloat1622float2(*(const __nv_bfloat162*)&u.y); f[2] = p.x; f[3] = p.y;
    p = __bfloat1622float2(*(const __nv_bfloat162*)&u.z); f[4] = p.x; f[5] = p.y;
    p = __bfloat1622float2(*(const __nv_bfloat162*)&u.w); f[6] = p.x; f[7] = p.y;
}

__device__ __forceinline__ unsigned f2tf(float f) {
    unsigned u;
    asm("cvt.rna.tf32.f32 %0, %1;" : "=r"(u) : "f"(f));
    return u;
}

// ---------------- prep: detect index dtype + zero degree array ----------
__global__ void prep_k(const int* __restrict__ raw) {
    int n = blockIdx.x * blockDim.x + threadIdx.x;
    if (n < NN) g_deg[n] = 0;
    if (n == 0) {
        int acc = 0;
#pragma unroll 1
        for (int i = 1; i < 128; i += 2) acc |= raw[i];
        g_is64 = (acc == 0) ? 1 : 0;   // int64 LE: high words all zero
    }
}

__global__ void cvt_k(const int* __restrict__ eraw, const int* __restrict__ braw) {
    int e = blockIdx.x * blockDim.x + threadIdx.x;
    if (e >= NE) return;
    int s, d;
    if (g_is64) {
        const long long* p = (const long long*)eraw;
        s = (int)p[e];
        d = (int)p[(size_t)NE + e];
        if (e < NN) g_bat[e] = (int)((const long long*)braw)[e];
    } else {
        s = eraw[e];
        d = eraw[NE + e];
        if (e < NN) g_bat[e] = braw[e];
    }
    g_src[e] = s;
    g_dst[e] = d;
    atomicAdd(&g_deg[d], 1);
}

// single-block exclusive scan over g_deg -> g_row; inits g_cur
__global__ __launch_bounds__(1024) void scan_k() {
    __shared__ int wsum[32];
    __shared__ int s_carry;
    const int tid = threadIdx.x, lane = tid & 31, wid = tid >> 5;
    if (tid == 0) s_carry = 0;
    __syncthreads();
    for (int base = 0; base < NN; base += 1024) {
        int i = base + tid;
        int v = (i < NN) ? g_deg[i] : 0;
        int incl = v;
#pragma unroll
        for (int off = 1; off < 32; off <<= 1) {
            int t = __shfl_up_sync(0xFFFFFFFFu, incl, off);
            if (lane >= off) incl += t;
        }
        if (lane == 31) wsum[wid] = incl;
        __syncthreads();
        if (wid == 0) {
            int w = wsum[lane];
            int wi = w;
#pragma unroll
            for (int off = 1; off < 32; off <<= 1) {
                int t = __shfl_up_sync(0xFFFFFFFFu, wi, off);
                if (lane >= off) wi += t;
            }
            wsum[lane] = wi - w;
        }
        __syncthreads();
        int c = s_carry;
        int excl = c + wsum[wid] + incl - v;
        if (i < NN) {
            g_row[i] = excl;
            g_cur[i] = excl;
        }
        __syncthreads();
        if (tid == 1023) s_carry = c + wsum[31] + incl;
        __syncthreads();
    }
    if (tid == 0) g_row[NN] = s_carry;
}

// 4 edges per thread: 4 outstanding ATOMG chains hide the ~318cyc return latency
__global__ void place_k() {
    int base = (blockIdx.x * blockDim.x + threadIdx.x) * 4;
#pragma unroll
    for (int j = 0; j < 4; j++) {
        int e = base + j;
        if (e < NE) {
            int p = atomicAdd(&g_cur[g_dst[e]], 1);
            g_csr_src[p] = g_src[e];
        }
    }
}

// -------- tf32 tensor-core GEMM (R11/R12-proven, UNTOUCHED): fp32 A --------
// BM=128, BN=64, BK=16; 256 threads = 8 warps (4m x 2n), warp tile 32x32.
__global__ __launch_bounds__(256) void mma_gemm_k(const float* __restrict__ A,
                                                  const float* __restrict__ B,
                                                  __nv_bfloat16* __restrict__ C,
                                                  int M, int N, int K) {
    constexpr int BM = 128, BN = 64, BK = 16;
    __shared__ unsigned As[BM][BK + 4];
    __shared__ unsigned Bs[BK][BN + 8];
    const int tid = threadIdx.x;
    const int lane = tid & 31, w = tid >> 5;
    const int wm = (w & 3) * 32, wn = (w >> 2) * 32;
    const int g = lane >> 2, tg = lane & 3;
    const int m0 = blockIdx.y * BM, n0 = blockIdx.x * BN;

    float c[2][4][4];
#pragma unroll
    for (int mt = 0; mt < 2; mt++)
#pragma unroll
        for (int nt = 0; nt < 4; nt++)
#pragma unroll
            for (int r = 0; r < 4; r++) c[mt][nt][r] = 0.f;

    for (int kb = 0; kb < K; kb += BK) {
        {   // A tile 128x16: 2 float4 per thread
            int row = tid >> 2, c4 = (tid & 3) * 4;
#pragma unroll
            for (int r = 0; r < 2; r++) {
                int rr = row + r * 64;
                float4 f = make_float4(0.f, 0.f, 0.f, 0.f);
                if (m0 + rr < M) f = *(const float4*)(A + (size_t)(m0 + rr) * K + kb + c4);
                As[rr][c4 + 0] = f2tf(f.x); As[rr][c4 + 1] = f2tf(f.y);
                As[rr][c4 + 2] = f2tf(f.z); As[rr][c4 + 3] = f2tf(f.w);
            }
        }
        {   // B tile 16x64: 1 float4 per thread
            int row = tid >> 4, c4 = (tid & 15) * 4;
            float4 f = *(const float4*)(B + (size_t)(kb + row) * N + n0 + c4);
            Bs[row][c4 + 0] = f2tf(f.x); Bs[row][c4 + 1] = f2tf(f.y);
            Bs[row][c4 + 2] = f2tf(f.z); Bs[row][c4 + 3] = f2tf(f.w);
        }
        __syncthreads();
#pragma unroll
        for (int kk = 0; kk < 2; kk++) {
            const int k0 = kk * 8;
            unsigned a[2][4], b[4][2];
#pragma unroll
            for (int mt = 0; mt < 2; mt++) {
                int r = wm + mt * 16;
                a[mt][0] = As[r + g][k0 + tg];
                a[mt][1] = As[r + g + 8][k0 + tg];
                a[mt][2] = As[r + g][k0 + tg + 4];
                a[mt][3] = As[r + g + 8][k0 + tg + 4];
            }
#pragma unroll
            for (int nt = 0; nt < 4; nt++) {
                int cc = wn + nt * 8 + g;
                b[nt][0] = Bs[k0 + tg][cc];
                b[nt][1] = Bs[k0 + tg + 4][cc];
            }
#pragma unroll
            for (int mt = 0; mt < 2; mt++)
#pragma unroll
                for (int nt = 0; nt < 4; nt++) {
                    asm volatile(
                        "mma.sync.aligned.m16n8k8.row.col.f32.tf32.tf32.f32 "
                        "{%0,%1,%2,%3}, {%4,%5,%6,%7}, {%8,%9}, {%0,%1,%2,%3};"
                        : "+f"(c[mt][nt][0]), "+f"(c[mt][nt][1]),
                          "+f"(c[mt][nt][2]), "+f"(c[mt][nt][3])
                        : "r"(a[mt][0]), "r"(a[mt][1]), "r"(a[mt][2]), "r"(a[mt][3]),
                          "r"(b[nt][0]), "r"(b[nt][1]));
                }
        }
        __syncthreads();
    }

#pragma unroll
    for (int mt = 0; mt < 2; mt++)
#pragma unroll
        for (int nt = 0; nt < 4; nt++) {
            int row0 = m0 + wm + mt * 16 + g;
            int col = n0 + wn + nt * 8 + tg * 2;
            if (row0 < M)
                *(__nv_bfloat162*)(C + (size_t)row0 * N + col) =
                    __floats2bfloat162_rn(c[mt][nt][0], c[mt][nt][1]);
            if (row0 + 8 < M)
                *(__nv_bfloat162*)(C + (size_t)(row0 + 8) * N + col) =
                    __floats2bfloat162_rn(c[mt][nt][2], c[mt][nt][3]);
        }
}

// -------- separate GEMM for layer 2: bf16 A (only A-loader differs) --------
__global__ __launch_bounds__(256) void mma_gemm_bf16_k(const __nv_bfloat16* __restrict__ A,
                                                       const float* __restrict__ B,
                                                       __nv_bfloat16* __restrict__ C,
                                                       int M, int N, int K) {
    constexpr int BM = 128, BN = 64, BK = 16;
    __shared__ unsigned As[BM][BK + 4];
    __shared__ unsigned Bs[BK][BN + 8];
    const int tid = threadIdx.x;
    const int lane = tid & 31, w = tid >> 5;
    const int wm = (w & 3) * 32, wn = (w >> 2) * 32;
    const int g = lane >> 2, tg = lane & 3;
    const int m0 = blockIdx.y * BM, n0 = blockIdx.x * BN;

    float c[2][4][4];
#pragma unroll
    for (int mt = 0; mt < 2; mt++)
#pragma unroll
        for (int nt = 0; nt < 4; nt++)
#pragma unroll
            for (int r = 0; r < 4; r++) c[mt][nt][r] = 0.f;

    for (int kb = 0; kb < K; kb += BK) {
        {   // A tile 128x16 bf16: 1 uint4 (8 elems) per thread
            int row = tid >> 1, c8 = (tid & 1) * 8;
            float f[8] = {0.f, 0.f, 0.f, 0.f, 0.f, 0.f, 0.f, 0.f};
            if (m0 + row < M)
                unp8(*(const uint4*)(A + (size_t)(m0 + row) * K + kb + c8), f);
#pragma unroll
            for (int j = 0; j < 8; j++) As[row][c8 + j] = f2tf(f[j]);
        }
        {   // B tile 16x64: 1 float4 per thread
            int row = tid >> 4, c4 = (tid & 15) * 4;
            float4 f = *(const float4*)(B + (size_t)(kb + row) * N + n0 + c4);
            Bs[row][c4 + 0] = f2tf(f.x); Bs[row][c4 + 1] = f2tf(f.y);
            Bs[row][c4 + 2] = f2tf(f.z); Bs[row][c4 + 3] = f2tf(f.w);
        }
        __syncthreads();
#pragma unroll
        for (int kk = 0; kk < 2; kk++) {
            const int k0 = kk * 8;
            unsigned a[2][4], b[4][2];
#pragma unroll
            for (int mt = 0; mt < 2; mt++) {
                int r = wm + mt * 16;
                a[mt][0] = As[r + g][k0 + tg];
                a[mt][1] = As[r + g + 8][k0 + tg];
                a[mt][2] = As[r + g][k0 + tg + 4];
                a[mt][3] = As[r + g + 8][k0 + tg + 4];
            }
#pragma unroll
            for (int nt = 0; nt < 4; nt++) {
                int cc = wn + nt * 8 + g;
                b[nt][0] = Bs[k0 + tg][cc];
                b[nt][1] = Bs[k0 + tg + 4][cc];
            }
#pragma unroll
            for (int mt = 0; mt < 2; mt++)
#pragma unroll
                for (int nt = 0; nt < 4; nt++) {
                    asm volatile(
                        "mma.sync.aligned.m16n8k8.row.col.f32.tf32.tf32.f32 "
                        "{%0,%1,%2,%3}, {%4,%5,%6,%7}, {%8,%9}, {%0,%1,%2,%3};"
                        : "+f"(c[mt][nt][0]), "+f"(c[mt][nt][1]),
                          "+f"(c[mt][nt][2]), "+f"(c[mt][nt][3])
                        : "r"(a[mt][0]), "r"(a[mt][1]), "r"(a[mt][2]), "r"(a[mt][3]),
                          "r"(b[nt][0]), "r"(b[nt][1]));
                }
        }
        __syncthreads();
    }

#pragma unroll
    for (int mt = 0; mt < 2; mt++)
#pragma unroll
        for (int nt = 0; nt < 4; nt++) {
            int row0 = m0 + wm + mt * 16 + g;
            int col = n0 + wn + nt * 8 + tg * 2;
            if (row0 < M)
                *(__nv_bfloat162*)(C + (size_t)row0 * N + col) =
                    __floats2bfloat162_rn(c[mt][nt][0], c[mt][nt][1]);
            if (row0 + 8 < M)
                *(__nv_bfloat162*)(C + (size_t)(row0 + 8) * N + col) =
                    __floats2bfloat162_rn(c[mt][nt][2], c[mt][nt][3]);
        }
}

// ---------------- attention coefficients (bf16 features) ----------------
__global__ void al1_k(const float* __restrict__ a_src, const float* __restrict__ a_dst) {
    int t = blockIdx.x * blockDim.x + threadIdx.x;
    if (t >= NN * HEADS) return;
    int n = t >> 2, h = t & 3;
    const uint4* hr = (const uint4*)(g_h1b + (size_t)n * D1 + h * HID);
    const float4* as = (const float4*)(a_src + h * HID);
    const float4* ad = (const float4*)(a_dst + h * HID);
    float ss = 0.f, sd = 0.f;
#pragma unroll
    for (int j = 0; j < 8; j++) {
        float f[8];
        unp8(hr[j], f);
        float4 a0 = as[2 * j], a1 = as[2 * j + 1];
        float4 b0 = ad[2 * j], b1 = ad[2 * j + 1];
        ss += f[0] * a0.x + f[1] * a0.y + f[2] * a0.z + f[3] * a0.w
            + f[4] * a1.x + f[5] * a1.y + f[6] * a1.z + f[7] * a1.w;
        sd += f[0] * b0.x + f[1] * b0.y + f[2] * b0.z + f[3] * b0.w
            + f[4] * b1.x + f[5] * b1.y + f[6] * b1.z + f[7] * b1.w;
    }
    g_als1[t] = ss;
    g_ald1[t] = sd;
}

// also zeroes the pooled output (independent work, saves a launch)
__global__ void al2_k(const float* __restrict__ a_src, const float* __restrict__ a_dst) {
    int n = blockIdx.x * blockDim.x + threadIdx.x;
    if (n < NG * HID) g_pool[n] = 0.f;
    if (n >= NN) return;
    const uint4* hr = (const uint4*)(g_h2b + (size_t)n * HID);
    const float4* as = (const float4*)a_src;
    const float4* ad = (const float4*)a_dst;
    float ss = 0.f, sd = 0.f;
#pragma unroll
    for (int j = 0; j < 8; j++) {
        float f[8];
        unp8(hr[j], f);
        float4 a0 = as[2 * j], a1 = as[2 * j + 1];
        float4 b0 = ad[2 * j], b1 = ad[2 * j + 1];
        ss += f[0] * a0.x + f[1] * a0.y + f[2] * a0.z + f[3] * a0.w
            + f[4] * a1.x + f[5] * a1.y + f[6] * a1.z + f[7] * a1.w;
        sd += f[0] * b0.x + f[1] * b0.y + f[2] * b0.z + f[3] * b0.w
            + f[4] * b1.x + f[5] * b1.y + f[6] * b1.z + f[7] * b1.w;
    }
    g_als2[n] = ss;
    g_ald2[n] = sd;
}

// ------- layer 1: fused single-pass softmax + aggregate + bias + relu -------
// warp per dst node; lane owns channels [lane*8, lane*8+8); bf16 out store.
__global__ __launch_bounds__(256) void agg1_k(const float* __restrict__ b1) {
    int node = (blockIdx.x * blockDim.x + threadIdx.x) >> 5;
    int lane = threadIdx.x & 31;
    if (node >= NN) return;
    const int h = lane >> 3;
    const int beg = g_row[node], end = g_row[node + 1];

    const float ald = g_ald1[node * 4 + h];
    float ex = __expf(leaky(g_als1[node * 4 + h] + ald));  // self-loop term
    float den = ex;
    float acc[8];
    {
        float f[8];
        unp8(*(const uint4*)(g_h1b + (size_t)node * D1 + lane * 8), f);
#pragma unroll
        for (int c = 0; c < 8; c++) acc[c] = ex * f[c];
    }
    for (int i = beg; i < end; i++) {
        int s = g_csr_src[i];
        float w = __expf(leaky(g_als1[s * 4 + h] + ald));
        den += w;
        float f[8];
        unp8(*(const uint4*)(g_h1b + (size_t)s * D1 + lane * 8), f);
#pragma unroll
        for (int c = 0; c < 8; c++) acc[c] = fmaf(w, f[c], acc[c]);
    }
    float inv = 1.f / (den + 1e-16f);
    const float4* bp = (const float4*)(b1 + lane * 8);
    float4 b0 = bp[0], b4 = bp[1];
    float o[8];
    o[0] = fmaxf(fmaf(acc[0], inv, b0.x), 0.f);
    o[1] = fmaxf(fmaf(acc[1], inv, b0.y), 0.f);
    o[2] = fmaxf(fmaf(acc[2], inv, b0.z), 0.f);
    o[3] = fmaxf(fmaf(acc[3], inv, b0.w), 0.f);
    o[4] = fmaxf(fmaf(acc[4], inv, b4.x), 0.f);
    o[5] = fmaxf(fmaf(acc[5], inv, b4.y), 0.f);
    o[6] = fmaxf(fmaf(acc[6], inv, b4.z), 0.f);
    o[7] = fmaxf(fmaf(acc[7], inv, b4.w), 0.f);
    uint4 pk;
    *(__nv_bfloat162*)&pk.x = __floats2bfloat162_rn(o[0], o[1]);
    *(__nv_bfloat162*)&pk.y = __floats2bfloat162_rn(o[2], o[3]);
    *(__nv_bfloat162*)&pk.z = __floats2bfloat162_rn(o[4], o[5]);
    *(__nv_bfloat162*)&pk.w = __floats2bfloat162_rn(o[6], o[7]);
    *(uint4*)(g_out1b + (size_t)node * D1 + lane * 8) = pk;
}

// ------- layer 2: fused single-pass softmax + aggregate + bias + pool -------
__global__ __launch_bounds__(256) void agg2_k(const float* __restrict__ b2) {
    int node = (blockIdx.x * blockDim.x + threadIdx.x) >> 5;
    int lane = threadIdx.x & 31;
    if (node >= NN) return;
    const int beg = g_row[node], end = g_row[node + 1];

    const float ald = g_ald2[node];
    float ex = __expf(leaky(g_als2[node] + ald));
    float den = ex;
    float a0, a1;
    {
        float2 v = __bfloat1622float2(
            *(const __nv_bfloat162*)(g_h2b + (size_t)node * HID + lane * 2));
        a0 = ex * v.x; a1 = ex * v.y;
    }
    for (int i = beg; i < end; i++) {
        int s = g_csr_src[i];
        float w = __expf(leaky(g_als2[s] + ald));
        den += w;
        float2 v = __bfloat1622float2(
            *(const __nv_bfloat162*)(g_h2b + (size_t)s * HID + lane * 2));
        a0 = fmaf(w, v.x, a0);
        a1 = fmaf(w, v.y, a1);
    }
    float inv = 1.f / (den + 1e-16f);
    float2 bb = *(const float2*)(b2 + lane * 2);
    float v0 = fmaf(a0, inv, bb.x);
    float v1 = fmaf(a1, inv, bb.y);

    float u0 = __shfl_down_sync(0xFFFFFFFFu, v0, 1);
    float u1 = __shfl_down_sync(0xFFFFFFFFu, v1, 1);
    if ((lane & 1) == 0) {
        int g = g_bat[node];
        red4(&g_pool[g * HID + lane * 2], make_float4(v0, v1, u0, u1));
    }
}

// ---------------- classifier ----------------
__global__ void cls_k(const float* __restrict__ fcw, const float* __restrict__ fcb,
                      float* __restrict__ out) {
    int g = blockIdx.x * blockDim.x + threadIdx.x;
    if (g >= NG) return;
    float l[OUTC];
#pragma unroll
    for (int j = 0; j < OUTC; j++) l[j] = fcb[j];
    for (int k = 0; k < HID; k++) {
        float p = g_pool[g * HID + k];
#pragma unroll
        for (int j = 0; j < OUTC; j++) l[j] = fmaf(p, fcw[k * OUTC + j], l[j]);
    }
    float mx = l[0];
#pragma unroll
    for (int j = 1; j < OUTC; j++) mx = fmaxf(mx, l[j]);
    float s = 0.f;
#pragma unroll
    for (int j = 0; j < OUTC; j++) s += expf(l[j] - mx);
    float lse = mx + logf(s);
#pragma unroll
    for (int j = 0; j < OUTC; j++) out[g * OUTC + j] = l[j] - lse;
}

// ---------------- launch ----------------
extern "C" void kernel_launch(void* const* d_in, const int* in_sizes, int n_in,
                              void* d_out, int out_size) {
    const float* x      = (const float*)d_in[0];
    const int*   ei_raw = (const int*)d_in[1];
    const int*   b_raw  = (const int*)d_in[2];
    const float* W1     = (const float*)d_in[3];
    const float* a_src1 = (const float*)d_in[4];
    const float* a_dst1 = (const float*)d_in[5];
    const float* b1     = (const float*)d_in[6];
    const float* W2     = (const float*)d_in[7];
    const float* a_src2 = (const float*)d_in[8];
    const float* a_dst2 = (const float*)d_in[9];
    const float* b2     = (const float*)d_in[10];
    const float* fcw    = (const float*)d_in[11];
    const float* fcb    = (const float*)d_in[12];
    float*       out    = (float*)d_out;

    void *p_h1b, *p_out1b, *p_h2b;
    cudaGetSymbolAddress(&p_h1b, g_h1b);
    cudaGetSymbolAddress(&p_out1b, g_out1b);
    cudaGetSymbolAddress(&p_h2b, g_h2b);

    // one-time stream/event creation (first call is the uncaptured correctness
    // run; later captured calls reuse them — no allocs during capture)
    static cudaStream_t s_aux = nullptr;
    static cudaEvent_t ev_fork = nullptr, ev_join = nullptr;
    if (s_aux == nullptr) {
        cudaStreamCreateWithFlags(&s_aux, cudaStreamNonBlocking);
        cudaEventCreateWithFlags(&ev_fork, cudaEventDisableTiming);
        cudaEventCreateWithFlags(&ev_join, cudaEventDisableTiming);
    }

    const int T = 256;
    const int gN4 = (NN * HEADS + T - 1) / T;
    const int gN  = (NN + T - 1) / T;
    const int gE  = (NE + T - 1) / T;
    const int gE4 = (NE + T * 4 - 1) / (T * 4);
    const int gNw = (NN * 32 + T - 1) / T;   // warp per node
    const int gM  = (NN + 127) / 128;

    // ---- fork: CSR build chain on s_aux, concurrent with GEMM1 chain ----
    cudaEventRecord(ev_fork, 0);
    cudaStreamWaitEvent(s_aux, ev_fork, 0);
    prep_k<<<gN, T, 0, s_aux>>>(ei_raw);
    cvt_k<<<gE, T, 0, s_aux>>>(ei_raw, b_raw);
    scan_k<<<1, 1024, 0, s_aux>>>();
    place_k<<<gE4, T, 0, s_aux>>>();
    cudaEventRecord(ev_join, s_aux);

    // ---- GAT layer 1 feature chain (independent of CSR) ----
    mma_gemm_k<<<dim3(D1 / 64, gM), 256>>>(x, W1, (__nv_bfloat16*)p_h1b, NN, D1, INC);
    al1_k<<<gN4, T>>>(a_src1, a_dst1);

    // ---- join: aggregation needs both chains ----
    cudaStreamWaitEvent(0, ev_join, 0);
    agg1_k<<<gNw, T>>>(b1);

    // ---- GAT layer 2 (+ fused pooling) ----
    mma_gemm_bf16_k<<<dim3(HID / 64, gM), 256>>>((const __nv_bfloat16*)p_out1b, W2,
                                                 (__nv_bfloat16*)p_h2b, NN, HID, D1);
    al2_k<<<gN, T>>>(a_src2, a_dst2);
    agg2_k<<<gNw, T>>>(b2);

    // ---- classifier ----
    cls_k<<<(NG + T - 1) / T, T>>>(fcw, fcb, out);
}

// round 15
// speedup vs baseline: 1.4341x; 1.4341x over previous
#include <cuda_runtime.h>
#include <cuda_bf16.h>
#include <cstdint>
#include <cstddef>

#define NN     50000
#define NE     800000
#define INC    128
#define HID    64
#define HEADS  4
#define D1     256          // HEADS*HID
#define OUTC   10
#define NG     500
#define NEG    0.2f

// ---------------- scratch (device globals; allocation-free) ----------------
__device__ __align__(16) __nv_bfloat16 g_h1b[NN * D1];   // x @ W1   (bf16)
__device__ __align__(16) float         g_out1[NN * D1];  // relu(GAT1 + b1) fp32
__device__ __align__(16) __nv_bfloat16 g_h2b[NN * HID];  // out1 @ W2 (bf16)
__device__ __align__(16) float g_als1[NN * HEADS];
__device__ __align__(16) float g_ald1[NN * HEADS];
__device__ float g_als2[NN], g_ald2[NN];
__device__ __align__(16) float g_pool[NG * HID];

// index handling + CSR (dst-sorted)
__device__ int g_is64;
__device__ int g_src[NE];
__device__ int g_dst[NE];
__device__ int g_bat[NN];
__device__ int g_deg[NN];
__device__ int g_row[NN + 1];
__device__ int g_cur[NN];
__device__ int g_csr_src[NE];

// ---------------- helpers ----------------
__device__ __forceinline__ float leaky(float v) { return v > 0.f ? v : NEG * v; }

__device__ __forceinline__ void red4(float* p, float4 v) {
    asm volatile("red.global.add.v4.f32 [%0], {%1,%2,%3,%4};"
                 :: "l"(p), "f"(v.x), "f"(v.y), "f"(v.z), "f"(v.w) : "memory");
}

__device__ __forceinline__ void unp8(uint4 u, float* f) {
    float2 p;
    p = __bfloat1622float2(*(const __nv_bfloat162*)&u.x); f[0] = p.x; f[1] = p.y;
    p = __bfloat1622float2(*(const __nv_bfloat162*)&u.y); f[2] = p.x; f[3] = p.y;
    p = __bfloat1622float2(*(const __nv_bfloat162*)&u.z); f[4] = p.x; f[5] = p.y;
    p = __bfloat1622float2(*(const __nv_bfloat162*)&u.w); f[6] = p.x; f[7] = p.y;
}

__device__ __forceinline__ unsigned f2tf(float f) {
    unsigned u;
    asm("cvt.rna.tf32.f32 %0, %1;" : "=r"(u) : "f"(f));
    return u;
}

// ---------------- prep: detect index dtype + zero degree array ----------
__global__ void prep_k(const int* __restrict__ raw) {
    int n = blockIdx.x * blockDim.x + threadIdx.x;
    if (n < NN) g_deg[n] = 0;
    if (n == 0) {
        int acc = 0;
#pragma unroll 1
        for (int i = 1; i < 128; i += 2) acc |= raw[i];
        g_is64 = (acc == 0) ? 1 : 0;   // int64 LE: high words all zero
    }
}

__global__ void cvt_k(const int* __restrict__ eraw, const int* __restrict__ braw) {
    int e = blockIdx.x * blockDim.x + threadIdx.x;
    if (e >= NE) return;
    int s, d;
    if (g_is64) {
        const long long* p = (const long long*)eraw;
        s = (int)p[e];
        d = (int)p[(size_t)NE + e];
        if (e < NN) g_bat[e] = (int)((const long long*)braw)[e];
    } else {
        s = eraw[e];
        d = eraw[NE + e];
        if (e < NN) g_bat[e] = braw[e];
    }
    g_src[e] = s;
    g_dst[e] = d;
    atomicAdd(&g_deg[d], 1);
}

// single-block exclusive scan over g_deg -> g_row; inits g_cur
__global__ __launch_bounds__(1024) void scan_k() {
    __shared__ int wsum[32];
    __shared__ int s_carry;
    const int tid = threadIdx.x, lane = tid & 31, wid = tid >> 5;
    if (tid == 0) s_carry = 0;
    __syncthreads();
    for (int base = 0; base < NN; base += 1024) {
        int i = base + tid;
        int v = (i < NN) ? g_deg[i] : 0;
        int incl = v;
#pragma unroll
        for (int off = 1; off < 32; off <<= 1) {
            int t = __shfl_up_sync(0xFFFFFFFFu, incl, off);
            if (lane >= off) incl += t;
        }
        if (lane == 31) wsum[wid] = incl;
        __syncthreads();
        if (wid == 0) {
            int w = wsum[lane];
            int wi = w;
#pragma unroll
            for (int off = 1; off < 32; off <<= 1) {
                int t = __shfl_up_sync(0xFFFFFFFFu, wi, off);
                if (lane >= off) wi += t;
            }
            wsum[lane] = wi - w;
        }
        __syncthreads();
        int c = s_carry;
        int excl = c + wsum[wid] + incl - v;
        if (i < NN) {
            g_row[i] = excl;
            g_cur[i] = excl;
        }
        __syncthreads();
        if (tid == 1023) s_carry = c + wsum[31] + incl;
        __syncthreads();
    }
    if (tid == 0) g_row[NN] = s_carry;
}

__global__ void place_k() {
    int e = blockIdx.x * blockDim.x + threadIdx.x;
    if (e >= NE) return;
    int p = atomicAdd(&g_cur[g_dst[e]], 1);
    g_csr_src[p] = g_src[e];
}

// -------- tf32 tensor-core GEMM (R11/R12-proven, UNTOUCHED) ----------------
// BM=128, BN=64, BK=16; 256 threads = 8 warps (4m x 2n), warp tile 32x32.
__global__ __launch_bounds__(256) void mma_gemm_k(const float* __restrict__ A,
                                                  const float* __restrict__ B,
                                                  __nv_bfloat16* __restrict__ C,
                                                  int M, int N, int K) {
    constexpr int BM = 128, BN = 64, BK = 16;
    __shared__ unsigned As[BM][BK + 4];
    __shared__ unsigned Bs[BK][BN + 8];
    const int tid = threadIdx.x;
    const int lane = tid & 31, w = tid >> 5;
    const int wm = (w & 3) * 32, wn = (w >> 2) * 32;
    const int g = lane >> 2, tg = lane & 3;
    const int m0 = blockIdx.y * BM, n0 = blockIdx.x * BN;

    float c[2][4][4];
#pragma unroll
    for (int mt = 0; mt < 2; mt++)
#pragma unroll
        for (int nt = 0; nt < 4; nt++)
#pragma unroll
            for (int r = 0; r < 4; r++) c[mt][nt][r] = 0.f;

    for (int kb = 0; kb < K; kb += BK) {
        {   // A tile 128x16: 2 float4 per thread
            int row = tid >> 2, c4 = (tid & 3) * 4;
#pragma unroll
            for (int r = 0; r < 2; r++) {
                int rr = row + r * 64;
                float4 f = make_float4(0.f, 0.f, 0.f, 0.f);
                if (m0 + rr < M) f = *(const float4*)(A + (size_t)(m0 + rr) * K + kb + c4);
                As[rr][c4 + 0] = f2tf(f.x); As[rr][c4 + 1] = f2tf(f.y);
                As[rr][c4 + 2] = f2tf(f.z); As[rr][c4 + 3] = f2tf(f.w);
            }
        }
        {   // B tile 16x64: 1 float4 per thread
            int row = tid >> 4, c4 = (tid & 15) * 4;
            float4 f = *(const float4*)(B + (size_t)(kb + row) * N + n0 + c4);
            Bs[row][c4 + 0] = f2tf(f.x); Bs[row][c4 + 1] = f2tf(f.y);
            Bs[row][c4 + 2] = f2tf(f.z); Bs[row][c4 + 3] = f2tf(f.w);
        }
        __syncthreads();
#pragma unroll
        for (int kk = 0; kk < 2; kk++) {
            const int k0 = kk * 8;
            unsigned a[2][4], b[4][2];
#pragma unroll
            for (int mt = 0; mt < 2; mt++) {
                int r = wm + mt * 16;
                a[mt][0] = As[r + g][k0 + tg];
                a[mt][1] = As[r + g + 8][k0 + tg];
                a[mt][2] = As[r + g][k0 + tg + 4];
                a[mt][3] = As[r + g + 8][k0 + tg + 4];
            }
#pragma unroll
            for (int nt = 0; nt < 4; nt++) {
                int cc = wn + nt * 8 + g;
                b[nt][0] = Bs[k0 + tg][cc];
                b[nt][1] = Bs[k0 + tg + 4][cc];
            }
#pragma unroll
            for (int mt = 0; mt < 2; mt++)
#pragma unroll
                for (int nt = 0; nt < 4; nt++) {
                    asm volatile(
                        "mma.sync.aligned.m16n8k8.row.col.f32.tf32.tf32.f32 "
                        "{%0,%1,%2,%3}, {%4,%5,%6,%7}, {%8,%9}, {%0,%1,%2,%3};"
                        : "+f"(c[mt][nt][0]), "+f"(c[mt][nt][1]),
                          "+f"(c[mt][nt][2]), "+f"(c[mt][nt][3])
                        : "r"(a[mt][0]), "r"(a[mt][1]), "r"(a[mt][2]), "r"(a[mt][3]),
                          "r"(b[nt][0]), "r"(b[nt][1]));
                }
        }
        __syncthreads();
    }

#pragma unroll
    for (int mt = 0; mt < 2; mt++)
#pragma unroll
        for (int nt = 0; nt < 4; nt++) {
            int row0 = m0 + wm + mt * 16 + g;
            int col = n0 + wn + nt * 8 + tg * 2;
            if (row0 < M)
                *(__nv_bfloat162*)(C + (size_t)row0 * N + col) =
                    __floats2bfloat162_rn(c[mt][nt][0], c[mt][nt][1]);
            if (row0 + 8 < M)
                *(__nv_bfloat162*)(C + (size_t)(row0 + 8) * N + col) =
                    __floats2bfloat162_rn(c[mt][nt][2], c[mt][nt][3]);
        }
}

// ---------------- attention coefficients (bf16 features) ----------------
__global__ void al1_k(const float* __restrict__ a_src, const float* __restrict__ a_dst) {
    int t = blockIdx.x * blockDim.x + threadIdx.x;
    if (t >= NN * HEADS) return;
    int n = t >> 2, h = t & 3;
    const uint4* hr = (const uint4*)(g_h1b + (size_t)n * D1 + h * HID);
    const float4* as = (const float4*)(a_src + h * HID);
    const float4* ad = (const float4*)(a_dst + h * HID);
    float ss = 0.f, sd = 0.f;
#pragma unroll
    for (int j = 0; j < 8; j++) {
        float f[8];
        unp8(hr[j], f);
        float4 a0 = as[2 * j], a1 = as[2 * j + 1];
        float4 b0 = ad[2 * j], b1 = ad[2 * j + 1];
        ss += f[0] * a0.x + f[1] * a0.y + f[2] * a0.z + f[3] * a0.w
            + f[4] * a1.x + f[5] * a1.y + f[6] * a1.z + f[7] * a1.w;
        sd += f[0] * b0.x + f[1] * b0.y + f[2] * b0.z + f[3] * b0.w
            + f[4] * b1.x + f[5] * b1.y + f[6] * b1.z + f[7] * b1.w;
    }
    g_als1[t] = ss;
    g_ald1[t] = sd;
}

// also zeroes the pooled output (independent work, saves a launch)
__global__ void al2_k(const float* __restrict__ a_src, const float* __restrict__ a_dst) {
    int n = blockIdx.x * blockDim.x + threadIdx.x;
    if (n < NG * HID) g_pool[n] = 0.f;
    if (n >= NN) return;
    const uint4* hr = (const uint4*)(g_h2b + (size_t)n * HID);
    const float4* as = (const float4*)a_src;
    const float4* ad = (const float4*)a_dst;
    float ss = 0.f, sd = 0.f;
#pragma unroll
    for (int j = 0; j < 8; j++) {
        float f[8];
        unp8(hr[j], f);
        float4 a0 = as[2 * j], a1 = as[2 * j + 1];
        float4 b0 = ad[2 * j], b1 = ad[2 * j + 1];
        ss += f[0] * a0.x + f[1] * a0.y + f[2] * a0.z + f[3] * a0.w
            + f[4] * a1.x + f[5] * a1.y + f[6] * a1.z + f[7] * a1.w;
        sd += f[0] * b0.x + f[1] * b0.y + f[2] * b0.z + f[3] * b0.w
            + f[4] * b1.x + f[5] * b1.y + f[6] * b1.z + f[7] * b1.w;
    }
    g_als2[n] = ss;
    g_ald2[n] = sd;
}

// ------- layer 1: fused single-pass softmax + aggregate + bias + relu -------
// warp per dst node; lane owns channels [lane*8, lane*8+8), head h = lane>>3.
// Software-pipelined: index/logit/feature loads for edge i+1 issue before the
// FMAs of edge i, breaking the csr_src -> gather dependency chain (MLP 1 -> 2).
__global__ __launch_bounds__(256) void agg1_k(const float* __restrict__ b1) {
    int node = (blockIdx.x * blockDim.x + threadIdx.x) >> 5;
    int lane = threadIdx.x & 31;
    if (node >= NN) return;
    const int h = lane >> 3;
    const int beg = g_row[node], end = g_row[node + 1];

    const float ald = g_ald1[node * 4 + h];
    float ex = __expf(leaky(g_als1[node * 4 + h] + ald));  // self-loop term
    float den = ex;
    float acc[8];
    {
        float f[8];
        unp8(*(const uint4*)(g_h1b + (size_t)node * D1 + lane * 8), f);
#pragma unroll
        for (int c = 0; c < 8; c++) acc[c] = ex * f[c];
    }

    // pipeline prologue: loads for the first edge
    float alA = 0.f;
    uint4 hvA = make_uint4(0, 0, 0, 0);
    if (beg < end) {
        int s = g_csr_src[beg];
        alA = g_als1[s * 4 + h];
        hvA = *(const uint4*)(g_h1b + (size_t)s * D1 + lane * 8);
    }
    for (int i = beg; i < end; i++) {
        // issue next edge's loads before consuming current
        float alB = 0.f;
        uint4 hvB = make_uint4(0, 0, 0, 0);
        if (i + 1 < end) {
            int s = g_csr_src[i + 1];
            alB = g_als1[s * 4 + h];
            hvB = *(const uint4*)(g_h1b + (size_t)s * D1 + lane * 8);
        }
        float w = __expf(leaky(alA + ald));
        den += w;
        float f[8];
        unp8(hvA, f);
#pragma unroll
        for (int c = 0; c < 8; c++) acc[c] = fmaf(w, f[c], acc[c]);
        alA = alB;
        hvA = hvB;
    }

    float inv = 1.f / (den + 1e-16f);
    const float4* bp = (const float4*)(b1 + lane * 8);
    float4 b0 = bp[0], b4 = bp[1];
    float4 o0 = make_float4(fmaxf(fmaf(acc[0], inv, b0.x), 0.f),
                            fmaxf(fmaf(acc[1], inv, b0.y), 0.f),
                            fmaxf(fmaf(acc[2], inv, b0.z), 0.f),
                            fmaxf(fmaf(acc[3], inv, b0.w), 0.f));
    float4 o1 = make_float4(fmaxf(fmaf(acc[4], inv, b4.x), 0.f),
                            fmaxf(fmaf(acc[5], inv, b4.y), 0.f),
                            fmaxf(fmaf(acc[6], inv, b4.z), 0.f),
                            fmaxf(fmaf(acc[7], inv, b4.w), 0.f));
    float4* op = (float4*)(g_out1 + (size_t)node * D1 + lane * 8);
    op[0] = o0; op[1] = o1;
}

// ------- layer 2: fused single-pass softmax + aggregate + bias + pool -------
// warp per dst node; lane owns channels [lane*2, lane*2+2); pipelined likewise.
__global__ __launch_bounds__(256) void agg2_k(const float* __restrict__ b2) {
    int node = (blockIdx.x * blockDim.x + threadIdx.x) >> 5;
    int lane = threadIdx.x & 31;
    if (node >= NN) return;
    const int beg = g_row[node], end = g_row[node + 1];

    const float ald = g_ald2[node];
    float ex = __expf(leaky(g_als2[node] + ald));
    float den = ex;
    float a0, a1;
    {
        float2 v = __bfloat1622float2(
            *(const __nv_bfloat162*)(g_h2b + (size_t)node * HID + lane * 2));
        a0 = ex * v.x; a1 = ex * v.y;
    }

    float alA = 0.f;
    unsigned hvA = 0;
    if (beg < end) {
        int s = g_csr_src[beg];
        alA = g_als2[s];
        hvA = *(const unsigned*)(g_h2b + (size_t)s * HID + lane * 2);
    }
    for (int i = beg; i < end; i++) {
        float alB = 0.f;
        unsigned hvB = 0;
        if (i + 1 < end) {
            int s = g_csr_src[i + 1];
            alB = g_als2[s];
            hvB = *(const unsigned*)(g_h2b + (size_t)s * HID + lane * 2);
        }
        float w = __expf(leaky(alA + ald));
        den += w;
        float2 v = __bfloat1622float2(*(const __nv_bfloat162*)&hvA);
        a0 = fmaf(w, v.x, a0);
        a1 = fmaf(w, v.y, a1);
        alA = alB;
        hvA = hvB;
    }

    float inv = 1.f / (den + 1e-16f);
    float2 bb = *(const float2*)(b2 + lane * 2);
    float v0 = fmaf(a0, inv, bb.x);
    float v1 = fmaf(a1, inv, bb.y);

    float u0 = __shfl_down_sync(0xFFFFFFFFu, v0, 1);
    float u1 = __shfl_down_sync(0xFFFFFFFFu, v1, 1);
    if ((lane & 1) == 0) {
        int g = g_bat[node];
        red4(&g_pool[g * HID + lane * 2], make_float4(v0, v1, u0, u1));
    }
}

// ---------------- classifier ----------------
__global__ void cls_k(const float* __restrict__ fcw, const float* __restrict__ fcb,
                      float* __restrict__ out) {
    int g = blockIdx.x * blockDim.x + threadIdx.x;
    if (g >= NG) return;
    float l[OUTC];
#pragma unroll
    for (int j = 0; j < OUTC; j++) l[j] = fcb[j];
    for (int k = 0; k < HID; k++) {
        float p = g_pool[g * HID + k];
#pragma unroll
        for (int j = 0; j < OUTC; j++) l[j] = fmaf(p, fcw[k * OUTC + j], l[j]);
    }
    float mx = l[0];
#pragma unroll
    for (int j = 1; j < OUTC; j++) mx = fmaxf(mx, l[j]);
    float s = 0.f;
#pragma unroll
    for (int j = 0; j < OUTC; j++) s += expf(l[j] - mx);
    float lse = mx + logf(s);
#pragma unroll
    for (int j = 0; j < OUTC; j++) out[g * OUTC + j] = l[j] - lse;
}

// ---------------- launch ----------------
extern "C" void kernel_launch(void* const* d_in, const int* in_sizes, int n_in,
                              void* d_out, int out_size) {
    const float* x      = (const float*)d_in[0];
    const int*   ei_raw = (const int*)d_in[1];
    const int*   b_raw  = (const int*)d_in[2];
    const float* W1     = (const float*)d_in[3];
    const float* a_src1 = (const float*)d_in[4];
    const float* a_dst1 = (const float*)d_in[5];
    const float* b1     = (const float*)d_in[6];
    const float* W2     = (const float*)d_in[7];
    const float* a_src2 = (const float*)d_in[8];
    const float* a_dst2 = (const float*)d_in[9];
    const float* b2     = (const float*)d_in[10];
    const float* fcw    = (const float*)d_in[11];
    const float* fcb    = (const float*)d_in[12];
    float*       out    = (float*)d_out;

    void *p_h1b, *p_out1, *p_h2b;
    cudaGetSymbolAddress(&p_h1b, g_h1b);
    cudaGetSymbolAddress(&p_out1, g_out1);
    cudaGetSymbolAddress(&p_h2b, g_h2b);

    // one-time stream/event creation (first call is the uncaptured correctness
    // run; later captured calls reuse them — no allocs during capture)
    static cudaStream_t s_aux = nullptr;
    static cudaEvent_t ev_fork = nullptr, ev_join = nullptr;
    if (s_aux == nullptr) {
        cudaStreamCreateWithFlags(&s_aux, cudaStreamNonBlocking);
        cudaEventCreateWithFlags(&ev_fork, cudaEventDisableTiming);
        cudaEventCreateWithFlags(&ev_join, cudaEventDisableTiming);
    }

    const int T = 256;
    const int gN4 = (NN * HEADS + T - 1) / T;
    const int gN  = (NN + T - 1) / T;
    const int gE  = (NE + T - 1) / T;
    const int gNw = (NN * 32 + T - 1) / T;   // warp per node
    const int gM  = (NN + 127) / 128;

    // ---- fork: CSR build chain on s_aux, concurrent with GEMM1 chain ----
    cudaEventRecord(ev_fork, 0);
    cudaStreamWaitEvent(s_aux, ev_fork, 0);
    prep_k<<<gN, T, 0, s_aux>>>(ei_raw);
    cvt_k<<<gE, T, 0, s_aux>>>(ei_raw, b_raw);
    scan_k<<<1, 1024, 0, s_aux>>>();
    place_k<<<gE, T, 0, s_aux>>>();
    cudaEventRecord(ev_join, s_aux);

    // ---- GAT layer 1 feature chain (independent of CSR) ----
    mma_gemm_k<<<dim3(D1 / 64, gM), 256>>>(x, W1, (__nv_bfloat16*)p_h1b, NN, D1, INC);
    al1_k<<<gN4, T>>>(a_src1, a_dst1);

    // ---- join: aggregation needs both chains ----
    cudaStreamWaitEvent(0, ev_join, 0);
    agg1_k<<<gNw, T>>>(b1);

    // ---- GAT layer 2 (+ fused pooling) ----
    mma_gemm_k<<<dim3(HID / 64, gM), 256>>>((const float*)p_out1, W2,
                                            (__nv_bfloat16*)p_h2b, NN, HID, D1);
    al2_k<<<gN, T>>>(a_src2, a_dst2);
    agg2_k<<<gNw, T>>>(b2);

    // ---- classifier ----
    cls_k<<<(NG + T - 1) / T, T>>>(fcw, fcb, out);
}

// round 16
// speedup vs baseline: 1.4437x; 1.0067x over previous
#include <cuda_runtime.h>
#include <cuda_bf16.h>
#include <cstdint>
#include <cstddef>

#define NN     50000
#define NE     800000
#define INC    128
#define HID    64
#define HEADS  4
#define D1     256          // HEADS*HID
#define OUTC   10
#define NG     500
#define NEG    0.2f

// ---------------- scratch (device globals; allocation-free) ----------------
__device__ __align__(16) __nv_bfloat16 g_h1b[NN * D1];   // x @ W1   (bf16)
__device__ __align__(16) float         g_out1[NN * D1];  // relu(GAT1 + b1) fp32
__device__ __align__(16) __nv_bfloat16 g_h2b[NN * HID];  // out1 @ W2 (bf16)
__device__ __align__(16) float g_als1[NN * HEADS];
__device__ __align__(16) float g_ald1[NN * HEADS];
__device__ float g_als2[NN], g_ald2[NN];
__device__ __align__(16) float g_pool[NG * HID];

// index handling + CSR (dst-sorted)
__device__ int g_is64;
__device__ int g_src[NE];
__device__ int g_dst[NE];
__device__ int g_bat[NN];
__device__ int g_deg[NN];
__device__ int g_row[NN + 1];
__device__ int g_cur[NN];
__device__ int g_csr_src[NE];

// ---------------- helpers ----------------
__device__ __forceinline__ float leaky(float v) { return v > 0.f ? v : NEG * v; }

__device__ __forceinline__ void red4(float* p, float4 v) {
    asm volatile("red.global.add.v4.f32 [%0], {%1,%2,%3,%4};"
                 :: "l"(p), "f"(v.x), "f"(v.y), "f"(v.z), "f"(v.w) : "memory");
}

__device__ __forceinline__ void unp8(uint4 u, float* f) {
    float2 p;
    p = __bfloat1622float2(*(const __nv_bfloat162*)&u.x); f[0] = p.x; f[1] = p.y;
    p = __bfloat1622float2(*(const __nv_bfloat162*)&u.y); f[2] = p.x; f[3] = p.y;
    p = __bfloat1622float2(*(const __nv_bfloat162*)&u.z); f[4] = p.x; f[5] = p.y;
    p = __bfloat1622float2(*(const __nv_bfloat162*)&u.w); f[6] = p.x; f[7] = p.y;
}

__device__ __forceinline__ unsigned f2tf(float f) {
    unsigned u;
    asm("cvt.rna.tf32.f32 %0, %1;" : "=r"(u) : "f"(f));
    return u;
}

// ---------------- detect index dtype (1 warp; deg/pool zeroing -> memset) ---
__global__ void detect_k(const int* __restrict__ raw) {
    if (threadIdx.x == 0) {
        int acc = 0;
#pragma unroll 1
        for (int i = 1; i < 128; i += 2) acc |= raw[i];
        g_is64 = (acc == 0) ? 1 : 0;   // int64 LE: high words all zero
    }
}

__global__ void cvt_k(const int* __restrict__ eraw, const int* __restrict__ braw) {
    int e = blockIdx.x * blockDim.x + threadIdx.x;
    if (e >= NE) return;
    int s, d;
    if (g_is64) {
        const long long* p = (const long long*)eraw;
        s = (int)p[e];
        d = (int)p[(size_t)NE + e];
        if (e < NN) g_bat[e] = (int)((const long long*)braw)[e];
    } else {
        s = eraw[e];
        d = eraw[NE + e];
        if (e < NN) g_bat[e] = braw[e];
    }
    g_src[e] = s;
    g_dst[e] = d;
    atomicAdd(&g_deg[d], 1);
}

// single-block exclusive scan over g_deg -> g_row; inits g_cur
__global__ __launch_bounds__(1024) void scan_k() {
    __shared__ int wsum[32];
    __shared__ int s_carry;
    const int tid = threadIdx.x, lane = tid & 31, wid = tid >> 5;
    if (tid == 0) s_carry = 0;
    __syncthreads();
    for (int base = 0; base < NN; base += 1024) {
        int i = base + tid;
        int v = (i < NN) ? g_deg[i] : 0;
        int incl = v;
#pragma unroll
        for (int off = 1; off < 32; off <<= 1) {
            int t = __shfl_up_sync(0xFFFFFFFFu, incl, off);
            if (lane >= off) incl += t;
        }
        if (lane == 31) wsum[wid] = incl;
        __syncthreads();
        if (wid == 0) {
            int w = wsum[lane];
            int wi = w;
#pragma unroll
            for (int off = 1; off < 32; off <<= 1) {
                int t = __shfl_up_sync(0xFFFFFFFFu, wi, off);
                if (lane >= off) wi += t;
            }
            wsum[lane] = wi - w;
        }
        __syncthreads();
        int c = s_carry;
        int excl = c + wsum[wid] + incl - v;
        if (i < NN) {
            g_row[i] = excl;
            g_cur[i] = excl;
        }
        __syncthreads();
        if (tid == 1023) s_carry = c + wsum[31] + incl;
        __syncthreads();
    }
    if (tid == 0) g_row[NN] = s_carry;
}

__global__ void place_k() {
    int e = blockIdx.x * blockDim.x + threadIdx.x;
    if (e >= NE) return;
    int p = atomicAdd(&g_cur[g_dst[e]], 1);
    g_csr_src[p] = g_src[e];
}

// -------- tf32 tensor-core GEMM (R11/R12-proven, UNTOUCHED) ----------------
// BM=128, BN=64, BK=16; 256 threads = 8 warps (4m x 2n), warp tile 32x32.
__global__ __launch_bounds__(256) void mma_gemm_k(const float* __restrict__ A,
                                                  const float* __restrict__ B,
                                                  __nv_bfloat16* __restrict__ C,
                                                  int M, int N, int K) {
    constexpr int BM = 128, BN = 64, BK = 16;
    __shared__ unsigned As[BM][BK + 4];
    __shared__ unsigned Bs[BK][BN + 8];
    const int tid = threadIdx.x;
    const int lane = tid & 31, w = tid >> 5;
    const int wm = (w & 3) * 32, wn = (w >> 2) * 32;
    const int g = lane >> 2, tg = lane & 3;
    const int m0 = blockIdx.y * BM, n0 = blockIdx.x * BN;

    float c[2][4][4];
#pragma unroll
    for (int mt = 0; mt < 2; mt++)
#pragma unroll
        for (int nt = 0; nt < 4; nt++)
#pragma unroll
            for (int r = 0; r < 4; r++) c[mt][nt][r] = 0.f;

    for (int kb = 0; kb < K; kb += BK) {
        {   // A tile 128x16: 2 float4 per thread
            int row = tid >> 2, c4 = (tid & 3) * 4;
#pragma unroll
            for (int r = 0; r < 2; r++) {
                int rr = row + r * 64;
                float4 f = make_float4(0.f, 0.f, 0.f, 0.f);
                if (m0 + rr < M) f = *(const float4*)(A + (size_t)(m0 + rr) * K + kb + c4);
                As[rr][c4 + 0] = f2tf(f.x); As[rr][c4 + 1] = f2tf(f.y);
                As[rr][c4 + 2] = f2tf(f.z); As[rr][c4 + 3] = f2tf(f.w);
            }
        }
        {   // B tile 16x64: 1 float4 per thread
            int row = tid >> 4, c4 = (tid & 15) * 4;
            float4 f = *(const float4*)(B + (size_t)(kb + row) * N + n0 + c4);
            Bs[row][c4 + 0] = f2tf(f.x); Bs[row][c4 + 1] = f2tf(f.y);
            Bs[row][c4 + 2] = f2tf(f.z); Bs[row][c4 + 3] = f2tf(f.w);
        }
        __syncthreads();
#pragma unroll
        for (int kk = 0; kk < 2; kk++) {
            const int k0 = kk * 8;
            unsigned a[2][4], b[4][2];
#pragma unroll
            for (int mt = 0; mt < 2; mt++) {
                int r = wm + mt * 16;
                a[mt][0] = As[r + g][k0 + tg];
                a[mt][1] = As[r + g + 8][k0 + tg];
                a[mt][2] = As[r + g][k0 + tg + 4];
                a[mt][3] = As[r + g + 8][k0 + tg + 4];
            }
#pragma unroll
            for (int nt = 0; nt < 4; nt++) {
                int cc = wn + nt * 8 + g;
                b[nt][0] = Bs[k0 + tg][cc];
                b[nt][1] = Bs[k0 + tg + 4][cc];
            }
#pragma unroll
            for (int mt = 0; mt < 2; mt++)
#pragma unroll
                for (int nt = 0; nt < 4; nt++) {
                    asm volatile(
                        "mma.sync.aligned.m16n8k8.row.col.f32.tf32.tf32.f32 "
                        "{%0,%1,%2,%3}, {%4,%5,%6,%7}, {%8,%9}, {%0,%1,%2,%3};"
                        : "+f"(c[mt][nt][0]), "+f"(c[mt][nt][1]),
                          "+f"(c[mt][nt][2]), "+f"(c[mt][nt][3])
                        : "r"(a[mt][0]), "r"(a[mt][1]), "r"(a[mt][2]), "r"(a[mt][3]),
                          "r"(b[nt][0]), "r"(b[nt][1]));
                }
        }
        __syncthreads();
    }

#pragma unroll
    for (int mt = 0; mt < 2; mt++)
#pragma unroll
        for (int nt = 0; nt < 4; nt++) {
            int row0 = m0 + wm + mt * 16 + g;
            int col = n0 + wn + nt * 8 + tg * 2;
            if (row0 < M)
                *(__nv_bfloat162*)(C + (size_t)row0 * N + col) =
                    __floats2bfloat162_rn(c[mt][nt][0], c[mt][nt][1]);
            if (row0 + 8 < M)
                *(__nv_bfloat162*)(C + (size_t)(row0 + 8) * N + col) =
                    __floats2bfloat162_rn(c[mt][nt][2], c[mt][nt][3]);
        }
}

// ---------------- attention coefficients (bf16 features) ----------------
__global__ void al1_k(const float* __restrict__ a_src, const float* __restrict__ a_dst) {
    int t = blockIdx.x * blockDim.x + threadIdx.x;
    if (t >= NN * HEADS) return;
    int n = t >> 2, h = t & 3;
    const uint4* hr = (const uint4*)(g_h1b + (size_t)n * D1 + h * HID);
    const float4* as = (const float4*)(a_src + h * HID);
    const float4* ad = (const float4*)(a_dst + h * HID);
    float ss = 0.f, sd = 0.f;
#pragma unroll
    for (int j = 0; j < 8; j++) {
        float f[8];
        unp8(hr[j], f);
        float4 a0 = as[2 * j], a1 = as[2 * j + 1];
        float4 b0 = ad[2 * j], b1 = ad[2 * j + 1];
        ss += f[0] * a0.x + f[1] * a0.y + f[2] * a0.z + f[3] * a0.w
            + f[4] * a1.x + f[5] * a1.y + f[6] * a1.z + f[7] * a1.w;
        sd += f[0] * b0.x + f[1] * b0.y + f[2] * b0.z + f[3] * b0.w
            + f[4] * b1.x + f[5] * b1.y + f[6] * b1.z + f[7] * b1.w;
    }
    g_als1[t] = ss;
    g_ald1[t] = sd;
}

__global__ void al2_k(const float* __restrict__ a_src, const float* __restrict__ a_dst) {
    int n = blockIdx.x * blockDim.x + threadIdx.x;
    if (n >= NN) return;
    const uint4* hr = (const uint4*)(g_h2b + (size_t)n * HID);
    const float4* as = (const float4*)a_src;
    const float4* ad = (const float4*)a_dst;
    float ss = 0.f, sd = 0.f;
#pragma unroll
    for (int j = 0; j < 8; j++) {
        float f[8];
        unp8(hr[j], f);
        float4 a0 = as[2 * j], a1 = as[2 * j + 1];
        float4 b0 = ad[2 * j], b1 = ad[2 * j + 1];
        ss += f[0] * a0.x + f[1] * a0.y + f[2] * a0.z + f[3] * a0.w
            + f[4] * a1.x + f[5] * a1.y + f[6] * a1.z + f[7] * a1.w;
        sd += f[0] * b0.x + f[1] * b0.y + f[2] * b0.z + f[3] * b0.w
            + f[4] * b1.x + f[5] * b1.y + f[6] * b1.z + f[7] * b1.w;
    }
    g_als2[n] = ss;
    g_ald2[n] = sd;
}

// ------- layer 1: fused single-pass softmax + aggregate + bias + relu -------
// warp per dst node; lane owns channels [lane*8, lane*8+8), head h = lane>>3
__global__ __launch_bounds__(256) void agg1_k(const float* __restrict__ b1) {
    int node = (blockIdx.x * blockDim.x + threadIdx.x) >> 5;
    int lane = threadIdx.x & 31;
    if (node >= NN) return;
    const int h = lane >> 3;
    const int beg = g_row[node], end = g_row[node + 1];

    const float ald = g_ald1[node * 4 + h];
    float ex = __expf(leaky(g_als1[node * 4 + h] + ald));  // self-loop term
    float den = ex;
    float acc[8];
    {
        float f[8];
        unp8(*(const uint4*)(g_h1b + (size_t)node * D1 + lane * 8), f);
#pragma unroll
        for (int c = 0; c < 8; c++) acc[c] = ex * f[c];
    }
    for (int i = beg; i < end; i++) {
        int s = g_csr_src[i];
        float w = __expf(leaky(g_als1[s * 4 + h] + ald));
        den += w;
        float f[8];
        unp8(*(const uint4*)(g_h1b + (size_t)s * D1 + lane * 8), f);
#pragma unroll
        for (int c = 0; c < 8; c++) acc[c] = fmaf(w, f[c], acc[c]);
    }
    float inv = 1.f / (den + 1e-16f);
    const float4* bp = (const float4*)(b1 + lane * 8);
    float4 b0 = bp[0], b4 = bp[1];
    float4 o0 = make_float4(fmaxf(fmaf(acc[0], inv, b0.x), 0.f),
                            fmaxf(fmaf(acc[1], inv, b0.y), 0.f),
                            fmaxf(fmaf(acc[2], inv, b0.z), 0.f),
                            fmaxf(fmaf(acc[3], inv, b0.w), 0.f));
    float4 o1 = make_float4(fmaxf(fmaf(acc[4], inv, b4.x), 0.f),
                            fmaxf(fmaf(acc[5], inv, b4.y), 0.f),
                            fmaxf(fmaf(acc[6], inv, b4.z), 0.f),
                            fmaxf(fmaf(acc[7], inv, b4.w), 0.f));
    float4* op = (float4*)(g_out1 + (size_t)node * D1 + lane * 8);
    op[0] = o0; op[1] = o1;
}

// ------- layer 2: fused single-pass softmax + aggregate + bias + pool -------
__global__ __launch_bounds__(256) void agg2_k(const float* __restrict__ b2) {
    int node = (blockIdx.x * blockDim.x + threadIdx.x) >> 5;
    int lane = threadIdx.x & 31;
    if (node >= NN) return;
    const int beg = g_row[node], end = g_row[node + 1];

    const float ald = g_ald2[node];
    float ex = __expf(leaky(g_als2[node] + ald));
    float den = ex;
    float a0, a1;
    {
        float2 v = __bfloat1622float2(
            *(const __nv_bfloat162*)(g_h2b + (size_t)node * HID + lane * 2));
        a0 = ex * v.x; a1 = ex * v.y;
    }
    for (int i = beg; i < end; i++) {
        int s = g_csr_src[i];
        float w = __expf(leaky(g_als2[s] + ald));
        den += w;
        float2 v = __bfloat1622float2(
            *(const __nv_bfloat162*)(g_h2b + (size_t)s * HID + lane * 2));
        a0 = fmaf(w, v.x, a0);
        a1 = fmaf(w, v.y, a1);
    }
    float inv = 1.f / (den + 1e-16f);
    float2 bb = *(const float2*)(b2 + lane * 2);
    float v0 = fmaf(a0, inv, bb.x);
    float v1 = fmaf(a1, inv, bb.y);

    float u0 = __shfl_down_sync(0xFFFFFFFFu, v0, 1);
    float u1 = __shfl_down_sync(0xFFFFFFFFu, v1, 1);
    if ((lane & 1) == 0) {
        int g = g_bat[node];
        red4(&g_pool[g * HID + lane * 2], make_float4(v0, v1, u0, u1));
    }
}

// ---------------- classifier ----------------
__global__ void cls_k(const float* __restrict__ fcw, const float* __restrict__ fcb,
                      float* __restrict__ out) {
    int g = blockIdx.x * blockDim.x + threadIdx.x;
    if (g >= NG) return;
    float l[OUTC];
#pragma unroll
    for (int j = 0; j < OUTC; j++) l[j] = fcb[j];
    for (int k = 0; k < HID; k++) {
        float p = g_pool[g * HID + k];
#pragma unroll
        for (int j = 0; j < OUTC; j++) l[j] = fmaf(p, fcw[k * OUTC + j], l[j]);
    }
    float mx = l[0];
#pragma unroll
    for (int j = 1; j < OUTC; j++) mx = fmaxf(mx, l[j]);
    float s = 0.f;
#pragma unroll
    for (int j = 0; j < OUTC; j++) s += expf(l[j] - mx);
    float lse = mx + logf(s);
#pragma unroll
    for (int j = 0; j < OUTC; j++) out[g * OUTC + j] = l[j] - lse;
}

// ---------------- launch ----------------
extern "C" void kernel_launch(void* const* d_in, const int* in_sizes, int n_in,
                              void* d_out, int out_size) {
    const float* x      = (const float*)d_in[0];
    const int*   ei_raw = (const int*)d_in[1];
    const int*   b_raw  = (const int*)d_in[2];
    const float* W1     = (const float*)d_in[3];
    const float* a_src1 = (const float*)d_in[4];
    const float* a_dst1 = (const float*)d_in[5];
    const float* b1     = (const float*)d_in[6];
    const float* W2     = (const float*)d_in[7];
    const float* a_src2 = (const float*)d_in[8];
    const float* a_dst2 = (const float*)d_in[9];
    const float* b2     = (const float*)d_in[10];
    const float* fcw    = (const float*)d_in[11];
    const float* fcb    = (const float*)d_in[12];
    float*       out    = (float*)d_out;

    void *p_h1b, *p_out1, *p_h2b, *p_deg, *p_pool;
    cudaGetSymbolAddress(&p_h1b, g_h1b);
    cudaGetSymbolAddress(&p_out1, g_out1);
    cudaGetSymbolAddress(&p_h2b, g_h2b);
    cudaGetSymbolAddress(&p_deg, g_deg);
    cudaGetSymbolAddress(&p_pool, g_pool);

    // one-time stream/event creation (first call is the uncaptured correctness
    // run; later captured calls reuse them — no allocs during capture)
    static cudaStream_t s_aux = nullptr;
    static cudaEvent_t ev_fork = nullptr, ev_join = nullptr;
    if (s_aux == nullptr) {
        cudaStreamCreateWithFlags(&s_aux, cudaStreamNonBlocking);
        cudaEventCreateWithFlags(&ev_fork, cudaEventDisableTiming);
        cudaEventCreateWithFlags(&ev_join, cudaEventDisableTiming);
    }

    const int T = 256;
    const int gN4 = (NN * HEADS + T - 1) / T;
    const int gN  = (NN + T - 1) / T;
    const int gE  = (NE + T - 1) / T;
    const int gNw = (NN * 32 + T - 1) / T;   // warp per node
    const int gM  = (NN + 127) / 128;

    // ---- fork: CSR build chain on s_aux, concurrent with GEMM1 chain ----
    cudaEventRecord(ev_fork, 0);
    cudaStreamWaitEvent(s_aux, ev_fork, 0);
    cudaMemsetAsync(p_deg, 0, NN * sizeof(int), s_aux);          // graph memset node
    cudaMemsetAsync(p_pool, 0, NG * HID * sizeof(float), s_aux); // pool zero (pre-join)
    detect_k<<<1, 32, 0, s_aux>>>(ei_raw);
    cvt_k<<<gE, T, 0, s_aux>>>(ei_raw, b_raw);
    scan_k<<<1, 1024, 0, s_aux>>>();
    place_k<<<gE, T, 0, s_aux>>>();
    cudaEventRecord(ev_join, s_aux);

    // ---- GAT layer 1 feature chain (independent of CSR) ----
    mma_gemm_k<<<dim3(D1 / 64, gM), 256>>>(x, W1, (__nv_bfloat16*)p_h1b, NN, D1, INC);
    al1_k<<<gN4, T>>>(a_src1, a_dst1);

    // ---- join: aggregation needs both chains ----
    cudaStreamWaitEvent(0, ev_join, 0);
    agg1_k<<<gNw, T>>>(b1);

    // ---- GAT layer 2 (+ fused pooling) ----
    mma_gemm_k<<<dim3(HID / 64, gM), 256>>>((const float*)p_out1, W2,
                                            (__nv_bfloat16*)p_h2b, NN, HID, D1);
    al2_k<<<gN, T>>>(a_src2, a_dst2);
    agg2_k<<<gNw, T>>>(b2);

    // ---- classifier ----
    cls_k<<<(NG + T - 1) / T, T>>>(fcw, fcb, out);
}